// round 1
// baseline (speedup 1.0000x reference)
#include <cuda_runtime.h>
#include <math.h>

#define NMAX 50000
#define EMAX 800000

// ---------------- scratch (no allocation allowed) ----------------
__device__ __align__(16) float g_deg[NMAX];
__device__ __align__(16) float g_invrs[NMAX];
__device__ __align__(16) float g_norm[EMAX];
__device__ __align__(16) float g_y[4 * NMAX * 16];   // layer-1 projections y_k
__device__ __align__(16) float g_t[NMAX * 16];
__device__ __align__(16) float g_u[NMAX * 16];
__device__ __align__(16) float g_v[NMAX * 16];
__device__ __align__(16) float g_G[4 * NMAX * 16];   // layer-2 hops

// ---------------- small elementwise kernels ----------------
__global__ void k_zero(float* __restrict__ p, int n) {
  int i = blockIdx.x * blockDim.x + threadIdx.x;
  if (i < n) p[i] = 0.f;
}

__global__ void k_deg(const int* __restrict__ ei, float* __restrict__ deg, int E) {
  int e = blockIdx.x * blockDim.x + threadIdx.x;
  if (e < E) atomicAdd(&deg[ei[E + e]], 1.0f);
}

__global__ void k_dinv(float* __restrict__ deg, int n) {
  int i = blockIdx.x * blockDim.x + threadIdx.x;
  if (i < n) { float d = deg[i]; deg[i] = (d > 0.f) ? rsqrtf(d) : 0.f; }
}

__global__ void k_norm(const int* __restrict__ ei, const float* __restrict__ dinv,
                       float* __restrict__ nrm, int E) {
  int e = blockIdx.x * blockDim.x + threadIdx.x;
  if (e < E) nrm[e] = dinv[ei[e]] * dinv[ei[E + e]];
}

// warp per row: inv_rowsum = 1 / max(sum(x_row), 1e-8)
__global__ void k_invrs(const float* __restrict__ x, float* __restrict__ invrs, int n) {
  int w = (blockIdx.x * blockDim.x + threadIdx.x) >> 5;
  int lane = threadIdx.x & 31;
  if (w >= n) return;
  const float4* x4 = (const float4*)x;
  float4 v = x4[w * 32 + lane];
  float s = v.x + v.y + v.z + v.w;
  #pragma unroll
  for (int o = 16; o; o >>= 1) s += __shfl_xor_sync(0xffffffffu, s, o);
  if (lane == 0) invrs[w] = 1.0f / fmaxf(s, 1e-8f);
}

__global__ void k_copy4(float4* __restrict__ d, const float4* __restrict__ s, int n4) {
  int i = blockIdx.x * blockDim.x + threadIdx.x;
  if (i < n4) d[i] = s[i];
}

__global__ void k_zero4(float4* __restrict__ d, int n4) {
  int i = blockIdx.x * blockDim.x + threadIdx.x;
  if (i < n4) d[i] = make_float4(0.f, 0.f, 0.f, 0.f);
}

// out[dst] += norm * in[src], 16-wide features, 4 threads/edge, vector red
__global__ void k_scat(const int* __restrict__ ei, const float* __restrict__ nrm,
                       const float4* __restrict__ in, float* __restrict__ out, int E) {
  int idx = blockIdx.x * blockDim.x + threadIdx.x;
  int e = idx >> 2;
  if (e >= E) return;
  int j = idx & 3;
  int s = ei[e];
  int d = ei[E + e];
  float w = nrm[e];
  float4 v = in[(s << 2) + j];
  float* p = out + (d << 4) + (j << 2);
  asm volatile("red.global.add.v4.f32 [%0], {%1,%2,%3,%4};"
               :: "l"(p), "f"(w * v.x), "f"(w * v.y), "f"(w * v.z), "f"(w * v.w)
               : "memory");
}

__global__ void k_biasrelu(const float4* __restrict__ v, const float* __restrict__ b,
                           float4* __restrict__ out, int n4) {
  int i = blockIdx.x * blockDim.x + threadIdx.x;
  if (i >= n4) return;
  float4 t = v[i];
  float4 bb = *(const float4*)(b + ((i & 3) << 2));
  out[i] = make_float4(fmaxf(t.x + bb.x, 0.f), fmaxf(t.y + bb.y, 0.f),
                       fmaxf(t.z + bb.z, 0.f), fmaxf(t.w + bb.w, 0.f));
}

// ---------------- GEMM1: y[k][n][16] = (x/rowsum) @ W1[k], fused scale ----------------
// block: 256 thr, 128 rows x 64 cols, thread tile 8x4, K=128 chunked by 16
__global__ __launch_bounds__(256) void k_gemm1(
    const float* __restrict__ x, const float* __restrict__ W1,
    const float* __restrict__ invrs, float* __restrict__ y, int n) {
  __shared__ float Ws[128][64];   // Ws[d][k*16+f]
  __shared__ float Xs[128][16];   // rows x d-chunk (fully contiguous: conflict-free)
  int tid = threadIdx.x;
  int rowBase = blockIdx.x * 128;
  for (int s = tid; s < 8192; s += 256) {
    int d = s >> 6, c = s & 63;
    Ws[d][c] = W1[(((c >> 4) << 7) | d) * 16 + (c & 15)];
  }
  float4 acc[8];
  #pragma unroll
  for (int i = 0; i < 8; i++) acc[i] = make_float4(0.f, 0.f, 0.f, 0.f);
  int cg = tid & 15, rg = tid >> 4;
  const float4* x4 = (const float4*)x;
  for (int ch = 0; ch < 8; ch++) {
    __syncthreads();
    for (int s = tid; s < 512; s += 256) {
      int r = s >> 2, d4 = s & 3;
      int row = rowBase + r;
      float4 vv = make_float4(0.f, 0.f, 0.f, 0.f);
      if (row < n) vv = x4[row * 32 + (ch << 2) + d4];
      *(float4*)&Xs[r][d4 << 2] = vv;
    }
    __syncthreads();
    #pragma unroll
    for (int dq = 0; dq < 4; dq++) {
      int d0 = (ch << 4) + (dq << 2);
      float4 w0 = *(const float4*)&Ws[d0 + 0][cg << 2];
      float4 w1 = *(const float4*)&Ws[d0 + 1][cg << 2];
      float4 w2 = *(const float4*)&Ws[d0 + 2][cg << 2];
      float4 w3 = *(const float4*)&Ws[d0 + 3][cg << 2];
      #pragma unroll
      for (int i = 0; i < 8; i++) {
        float4 xv = *(const float4*)&Xs[(rg << 3) + i][dq << 2];
        acc[i].x += xv.x * w0.x + xv.y * w1.x + xv.z * w2.x + xv.w * w3.x;
        acc[i].y += xv.x * w0.y + xv.y * w1.y + xv.z * w2.y + xv.w * w3.y;
        acc[i].z += xv.x * w0.z + xv.y * w1.z + xv.z * w2.z + xv.w * w3.z;
        acc[i].w += xv.x * w0.w + xv.y * w1.w + xv.z * w2.w + xv.w * w3.w;
      }
    }
  }
  int k = cg >> 2;
  int f = (cg & 3) << 2;
  #pragma unroll
  for (int i = 0; i < 8; i++) {
    int r = rowBase + (rg << 3) + i;
    if (r < n) {
      float sc = invrs[r];
      float4 o = make_float4(acc[i].x * sc, acc[i].y * sc, acc[i].z * sc, acc[i].w * sc);
      *(float4*)&y[(k * n + r) * 16 + f] = o;
    }
  }
}

// ---------------- GEMM2: out[n][64] = sum_k G[k][n][:] @ W2[k] + b2 ----------------
__global__ __launch_bounds__(256) void k_gemm2(
    const float* __restrict__ G, const float* __restrict__ W2,
    const float* __restrict__ b2, float* __restrict__ out, int n) {
  __shared__ float Ws[64][64];    // W2 is already [k*16+d][64] row-major
  __shared__ float Gs[128][36];   // rows x 32-dim chunk, padded
  int tid = threadIdx.x;
  int rowBase = blockIdx.x * 128;
  for (int s = tid; s < 4096; s += 256) ((float*)Ws)[s] = W2[s];
  float4 acc[8];
  #pragma unroll
  for (int i = 0; i < 8; i++) acc[i] = make_float4(0.f, 0.f, 0.f, 0.f);
  int cg = tid & 15, rg = tid >> 4;
  for (int ch = 0; ch < 2; ch++) {
    __syncthreads();
    for (int s = tid; s < 1024; s += 256) {
      int kk = s >> 9, rem = s & 511;
      int r = rem >> 2, f4 = rem & 3;
      int row = rowBase + r;
      float4 vv = make_float4(0.f, 0.f, 0.f, 0.f);
      if (row < n) vv = *(const float4*)&G[(((ch << 1) | kk) * n + row) * 16 + (f4 << 2)];
      *(float4*)&Gs[r][(kk << 4) | (f4 << 2)] = vv;
    }
    __syncthreads();
    #pragma unroll
    for (int dq = 0; dq < 8; dq++) {
      int d0 = (ch << 5) + (dq << 2);
      float4 w0 = *(const float4*)&Ws[d0 + 0][cg << 2];
      float4 w1 = *(const float4*)&Ws[d0 + 1][cg << 2];
      float4 w2 = *(const float4*)&Ws[d0 + 2][cg << 2];
      float4 w3 = *(const float4*)&Ws[d0 + 3][cg << 2];
      #pragma unroll
      for (int i = 0; i < 8; i++) {
        float4 gv = *(const float4*)&Gs[(rg << 3) + i][dq << 2];
        acc[i].x += gv.x * w0.x + gv.y * w1.x + gv.z * w2.x + gv.w * w3.x;
        acc[i].y += gv.x * w0.y + gv.y * w1.y + gv.z * w2.y + gv.w * w3.y;
        acc[i].z += gv.x * w0.z + gv.y * w1.z + gv.z * w2.z + gv.w * w3.z;
        acc[i].w += gv.x * w0.w + gv.y * w1.w + gv.z * w2.w + gv.w * w3.w;
      }
    }
  }
  float4 bb = *(const float4*)&b2[cg << 2];
  #pragma unroll
  for (int i = 0; i < 8; i++) {
    int r = rowBase + (rg << 3) + i;
    if (r < n) {
      *(float4*)&out[r * 64 + (cg << 2)] = make_float4(
          acc[i].x + bb.x, acc[i].y + bb.y, acc[i].z + bb.z, acc[i].w + bb.w);
    }
  }
}

// ---------------- launch ----------------
extern "C" void kernel_launch(void* const* d_in, const int* in_sizes, int n_in,
                              void* d_out, int out_size) {
  (void)n_in; (void)out_size;
  const float* x  = (const float*)d_in[0];
  const int*   ei = (const int*)d_in[1];
  const float* W1 = (const float*)d_in[2];
  const float* b1 = (const float*)d_in[3];
  const float* W2 = (const float*)d_in[4];
  const float* b2 = (const float*)d_in[5];
  float* out = (float*)d_out;
  int n = in_sizes[0] / 128;
  int E = in_sizes[1] / 2;

  float *deg, *invrs, *nrm, *y, *t, *u, *v, *G;
  cudaGetSymbolAddress((void**)&deg,   g_deg);
  cudaGetSymbolAddress((void**)&invrs, g_invrs);
  cudaGetSymbolAddress((void**)&nrm,   g_norm);
  cudaGetSymbolAddress((void**)&y,     g_y);
  cudaGetSymbolAddress((void**)&t,     g_t);
  cudaGetSymbolAddress((void**)&u,     g_u);
  cudaGetSymbolAddress((void**)&v,     g_v);
  cudaGetSymbolAddress((void**)&G,     g_G);

  const int TB = 256;
  int gN  = (n + TB - 1) / TB;
  int gE  = (E + TB - 1) / TB;
  int gE4 = (E * 4 + TB - 1) / TB;
  int n4  = n * 4;
  int gN4 = (n4 + TB - 1) / TB;
  int gW  = (n * 32 + TB - 1) / TB;
  int gG  = (n + 127) / 128;

  // gcn_norm
  k_zero<<<gN, TB>>>(deg, n);
  k_deg<<<gE, TB>>>(ei, deg, E);
  k_dinv<<<gN, TB>>>(deg, n);
  k_norm<<<gE, TB>>>(ei, deg, nrm, E);

  // row-normalize scale + layer-1 projections
  k_invrs<<<gW, TB>>>(x, invrs, n);
  k_gemm1<<<gG, 256>>>(x, W1, invrs, y, n);

  // layer-1 Horner: v = y0 + A(y1 + A(y2 + A*y3))
  k_copy4<<<gN4, TB>>>((float4*)t, (const float4*)(y + 2 * n * 16), n4);
  k_scat<<<gE4, TB>>>(ei, nrm, (const float4*)(y + 3 * n * 16), t, E);
  k_copy4<<<gN4, TB>>>((float4*)u, (const float4*)(y + 1 * n * 16), n4);
  k_scat<<<gE4, TB>>>(ei, nrm, (const float4*)t, u, E);
  k_copy4<<<gN4, TB>>>((float4*)v, (const float4*)y, n4);
  k_scat<<<gE4, TB>>>(ei, nrm, (const float4*)u, v, E);
  k_biasrelu<<<gN4, TB>>>((const float4*)v, b1, (float4*)G, n4);

  // layer-2 hops: G[k+1] = A * G[k]
  for (int k = 0; k < 3; k++) {
    k_zero4<<<gN4, TB>>>((float4*)(G + (k + 1) * n * 16), n4);
    k_scat<<<gE4, TB>>>(ei, nrm, (const float4*)(G + k * n * 16), G + (k + 1) * n * 16, E);
  }

  // combine + bias
  k_gemm2<<<gG, 256>>>(G, W2, b2, out, n);
}

// round 2
// speedup vs baseline: 1.1315x; 1.1315x over previous
#include <cuda_runtime.h>
#include <math.h>

#define NMAX 50000
#define EMAX 800000

// ---------------- scratch (no allocation allowed) ----------------
__device__ __align__(16) int   g_cnt[NMAX];        // in-degree (counting-sort hist)
__device__ __align__(16) int   g_rp[NMAX];         // CSR row ptr (exclusive scan)
__device__ __align__(16) int   g_ofs[NMAX];        // fill cursors
__device__ __align__(16) int   g_bsum[64];         // scan block sums
__device__ __align__(16) float g_dinv[NMAX];
__device__ __align__(16) float g_invrs[NMAX];
__device__ __align__(16) float2 g_csr[EMAX];       // (src as int bits, weight)
__device__ __align__(16) float g_y[4 * NMAX * 16]; // layer-1 projections y_k
__device__ __align__(16) float g_t[NMAX * 16];
__device__ __align__(16) float g_u[NMAX * 16];
__device__ __align__(16) float g_G[4 * NMAX * 16]; // layer-2 hops

// ---------------- CSR build ----------------
__global__ void k_zero2(int* __restrict__ a, int* __restrict__ b, int n) {
  int i = blockIdx.x * blockDim.x + threadIdx.x;
  if (i < n) { a[i] = 0; b[i] = 0; }
}

__global__ void k_hist(const int* __restrict__ ei, int* __restrict__ cnt, int E) {
  int e = blockIdx.x * blockDim.x + threadIdx.x;
  if (e < E) atomicAdd(&cnt[ei[E + e]], 1);
}

__global__ void k_dinv(const int* __restrict__ cnt, float* __restrict__ dinv, int n) {
  int i = blockIdx.x * blockDim.x + threadIdx.x;
  if (i < n) { int c = cnt[i]; dinv[i] = (c > 0) ? rsqrtf((float)c) : 0.f; }
}

// exclusive scan, level 1: 1024-wide blocks
__global__ __launch_bounds__(1024) void k_scan1(const int* __restrict__ cnt,
                                                int* __restrict__ rp,
                                                int* __restrict__ bsum, int n) {
  __shared__ int sh[1024];
  int t = threadIdx.x;
  int i = blockIdx.x * 1024 + t;
  int v = (i < n) ? cnt[i] : 0;
  sh[t] = v;
  __syncthreads();
  #pragma unroll
  for (int o = 1; o < 1024; o <<= 1) {
    int p = (t >= o) ? sh[t - o] : 0;
    __syncthreads();
    sh[t] += p;
    __syncthreads();
  }
  if (i < n) rp[i] = sh[t] - v;
  if (t == 1023) bsum[blockIdx.x] = sh[1023];
}

// level 2: scan up to 64 block sums in one block (exclusive, in place)
__global__ void k_scan2(int* __restrict__ bsum, int nb) {
  __shared__ int sh[64];
  int t = threadIdx.x;
  int v = (t < nb) ? bsum[t] : 0;
  sh[t] = v;
  __syncthreads();
  #pragma unroll
  for (int o = 1; o < 64; o <<= 1) {
    int p = (t >= o) ? sh[t - o] : 0;
    __syncthreads();
    sh[t] += p;
    __syncthreads();
  }
  if (t < nb) bsum[t] = sh[t] - v;
}

// level 3: add block offsets
__global__ __launch_bounds__(1024) void k_scan3(int* __restrict__ rp,
                                                const int* __restrict__ bsum, int n) {
  int i = blockIdx.x * 1024 + threadIdx.x;
  if (i < n) rp[i] += bsum[blockIdx.x];
}

// fill CSR entries: (src, dinv[src]*dinv[dst]) sorted into dst buckets
__global__ void k_fill(const int* __restrict__ ei, const float* __restrict__ dinv,
                       const int* __restrict__ rp, int* __restrict__ ofs,
                       float2* __restrict__ csr, int E) {
  int e = blockIdx.x * blockDim.x + threadIdx.x;
  if (e >= E) return;
  int s = ei[e];
  int d = ei[E + e];
  int p = rp[d] + atomicAdd(&ofs[d], 1);
  csr[p] = make_float2(__int_as_float(s), dinv[s] * dinv[d]);
}

// ---------------- row-normalize scale ----------------
__global__ void k_invrs(const float* __restrict__ x, float* __restrict__ invrs, int n) {
  int w = (blockIdx.x * blockDim.x + threadIdx.x) >> 5;
  int lane = threadIdx.x & 31;
  if (w >= n) return;
  const float4* x4 = (const float4*)x;
  float4 v = x4[w * 32 + lane];
  float s = v.x + v.y + v.z + v.w;
  #pragma unroll
  for (int o = 16; o; o >>= 1) s += __shfl_xor_sync(0xffffffffu, s, o);
  if (lane == 0) invrs[w] = 1.0f / fmaxf(s, 1e-8f);
}

// ---------------- gather SpMM: out[r] = init[r] + sum_e w_e * in[src_e] ----------------
// 4 threads per row (one float4 feature quad each), 4-way unrolled edge loop.
// init==null -> zero init; bias!=null -> +bias, ReLU epilogue.
__global__ __launch_bounds__(256) void k_spmm(
    const int* __restrict__ rp, const int* __restrict__ cnt,
    const float2* __restrict__ csr, const float4* __restrict__ in,
    const float4* __restrict__ init, const float* __restrict__ bias,
    float4* __restrict__ out, int n) {
  int idx = blockIdx.x * blockDim.x + threadIdx.x;
  int r = idx >> 2;
  if (r >= n) return;
  int q = idx & 3;
  int start = __ldg(&rp[r]);
  int len = __ldg(&cnt[r]);
  float4 a0 = make_float4(0.f, 0.f, 0.f, 0.f);
  float4 a1 = make_float4(0.f, 0.f, 0.f, 0.f);
  if (init) a0 = init[(r << 2) + q];
  int i = 0;
  for (; i + 4 <= len; i += 4) {
    float2 e0 = __ldg(&csr[start + i + 0]);
    float2 e1 = __ldg(&csr[start + i + 1]);
    float2 e2 = __ldg(&csr[start + i + 2]);
    float2 e3 = __ldg(&csr[start + i + 3]);
    float4 v0 = __ldg(&in[(__float_as_int(e0.x) << 2) + q]);
    float4 v1 = __ldg(&in[(__float_as_int(e1.x) << 2) + q]);
    float4 v2 = __ldg(&in[(__float_as_int(e2.x) << 2) + q]);
    float4 v3 = __ldg(&in[(__float_as_int(e3.x) << 2) + q]);
    a0.x += e0.y * v0.x; a0.y += e0.y * v0.y; a0.z += e0.y * v0.z; a0.w += e0.y * v0.w;
    a1.x += e1.y * v1.x; a1.y += e1.y * v1.y; a1.z += e1.y * v1.z; a1.w += e1.y * v1.w;
    a0.x += e2.y * v2.x; a0.y += e2.y * v2.y; a0.z += e2.y * v2.z; a0.w += e2.y * v2.w;
    a1.x += e3.y * v3.x; a1.y += e3.y * v3.y; a1.z += e3.y * v3.z; a1.w += e3.y * v3.w;
  }
  for (; i < len; i++) {
    float2 e0 = __ldg(&csr[start + i]);
    float4 v0 = __ldg(&in[(__float_as_int(e0.x) << 2) + q]);
    a0.x += e0.y * v0.x; a0.y += e0.y * v0.y; a0.z += e0.y * v0.z; a0.w += e0.y * v0.w;
  }
  float4 acc = make_float4(a0.x + a1.x, a0.y + a1.y, a0.z + a1.z, a0.w + a1.w);
  if (bias) {
    float4 bb = ((const float4*)bias)[q];
    acc = make_float4(fmaxf(acc.x + bb.x, 0.f), fmaxf(acc.y + bb.y, 0.f),
                      fmaxf(acc.z + bb.z, 0.f), fmaxf(acc.w + bb.w, 0.f));
  }
  out[(r << 2) + q] = acc;
}

// ---------------- GEMM1: y[k][n][16] = (x/rowsum) @ W1[k], fused scale ----------------
__global__ __launch_bounds__(256) void k_gemm1(
    const float* __restrict__ x, const float* __restrict__ W1,
    const float* __restrict__ invrs, float* __restrict__ y, int n) {
  __shared__ float Ws[128][64];
  __shared__ float Xs[128][16];
  int tid = threadIdx.x;
  int rowBase = blockIdx.x * 128;
  for (int s = tid; s < 8192; s += 256) {
    int d = s >> 6, c = s & 63;
    Ws[d][c] = W1[(((c >> 4) << 7) | d) * 16 + (c & 15)];
  }
  float4 acc[8];
  #pragma unroll
  for (int i = 0; i < 8; i++) acc[i] = make_float4(0.f, 0.f, 0.f, 0.f);
  int cg = tid & 15, rg = tid >> 4;
  const float4* x4 = (const float4*)x;
  for (int ch = 0; ch < 8; ch++) {
    __syncthreads();
    for (int s = tid; s < 512; s += 256) {
      int r = s >> 2, d4 = s & 3;
      int row = rowBase + r;
      float4 vv = make_float4(0.f, 0.f, 0.f, 0.f);
      if (row < n) vv = x4[row * 32 + (ch << 2) + d4];
      *(float4*)&Xs[r][d4 << 2] = vv;
    }
    __syncthreads();
    #pragma unroll
    for (int dq = 0; dq < 4; dq++) {
      int d0 = (ch << 4) + (dq << 2);
      float4 w0 = *(const float4*)&Ws[d0 + 0][cg << 2];
      float4 w1 = *(const float4*)&Ws[d0 + 1][cg << 2];
      float4 w2 = *(const float4*)&Ws[d0 + 2][cg << 2];
      float4 w3 = *(const float4*)&Ws[d0 + 3][cg << 2];
      #pragma unroll
      for (int i = 0; i < 8; i++) {
        float4 xv = *(const float4*)&Xs[(rg << 3) + i][dq << 2];
        acc[i].x += xv.x * w0.x + xv.y * w1.x + xv.z * w2.x + xv.w * w3.x;
        acc[i].y += xv.x * w0.y + xv.y * w1.y + xv.z * w2.y + xv.w * w3.y;
        acc[i].z += xv.x * w0.z + xv.y * w1.z + xv.z * w2.z + xv.w * w3.z;
        acc[i].w += xv.x * w0.w + xv.y * w1.w + xv.z * w2.w + xv.w * w3.w;
      }
    }
  }
  int k = cg >> 2;
  int f = (cg & 3) << 2;
  #pragma unroll
  for (int i = 0; i < 8; i++) {
    int r = rowBase + (rg << 3) + i;
    if (r < n) {
      float sc = invrs[r];
      float4 o = make_float4(acc[i].x * sc, acc[i].y * sc, acc[i].z * sc, acc[i].w * sc);
      *(float4*)&y[(k * n + r) * 16 + f] = o;
    }
  }
}

// ---------------- GEMM2: out[n][64] = sum_k G[k][n][:] @ W2[k] + b2 ----------------
__global__ __launch_bounds__(256) void k_gemm2(
    const float* __restrict__ G, const float* __restrict__ W2,
    const float* __restrict__ b2, float* __restrict__ out, int n) {
  __shared__ float Ws[64][64];
  __shared__ float Gs[128][36];
  int tid = threadIdx.x;
  int rowBase = blockIdx.x * 128;
  for (int s = tid; s < 4096; s += 256) ((float*)Ws)[s] = W2[s];
  float4 acc[8];
  #pragma unroll
  for (int i = 0; i < 8; i++) acc[i] = make_float4(0.f, 0.f, 0.f, 0.f);
  int cg = tid & 15, rg = tid >> 4;
  for (int ch = 0; ch < 2; ch++) {
    __syncthreads();
    for (int s = tid; s < 1024; s += 256) {
      int kk = s >> 9, rem = s & 511;
      int r = rem >> 2, f4 = rem & 3;
      int row = rowBase + r;
      float4 vv = make_float4(0.f, 0.f, 0.f, 0.f);
      if (row < n) vv = *(const float4*)&G[(((ch << 1) | kk) * n + row) * 16 + (f4 << 2)];
      *(float4*)&Gs[r][(kk << 4) | (f4 << 2)] = vv;
    }
    __syncthreads();
    #pragma unroll
    for (int dq = 0; dq < 8; dq++) {
      int d0 = (ch << 5) + (dq << 2);
      float4 w0 = *(const float4*)&Ws[d0 + 0][cg << 2];
      float4 w1 = *(const float4*)&Ws[d0 + 1][cg << 2];
      float4 w2 = *(const float4*)&Ws[d0 + 2][cg << 2];
      float4 w3 = *(const float4*)&Ws[d0 + 3][cg << 2];
      #pragma unroll
      for (int i = 0; i < 8; i++) {
        float4 gv = *(const float4*)&Gs[(rg << 3) + i][dq << 2];
        acc[i].x += gv.x * w0.x + gv.y * w1.x + gv.z * w2.x + gv.w * w3.x;
        acc[i].y += gv.x * w0.y + gv.y * w1.y + gv.z * w2.y + gv.w * w3.y;
        acc[i].z += gv.x * w0.z + gv.y * w1.z + gv.z * w2.z + gv.w * w3.z;
        acc[i].w += gv.x * w0.w + gv.y * w1.w + gv.z * w2.w + gv.w * w3.w;
      }
    }
  }
  float4 bb = *(const float4*)&b2[cg << 2];
  #pragma unroll
  for (int i = 0; i < 8; i++) {
    int r = rowBase + (rg << 3) + i;
    if (r < n) {
      *(float4*)&out[r * 64 + (cg << 2)] = make_float4(
          acc[i].x + bb.x, acc[i].y + bb.y, acc[i].z + bb.z, acc[i].w + bb.w);
    }
  }
}

// ---------------- launch ----------------
extern "C" void kernel_launch(void* const* d_in, const int* in_sizes, int n_in,
                              void* d_out, int out_size) {
  (void)n_in; (void)out_size;
  const float* x  = (const float*)d_in[0];
  const int*   ei = (const int*)d_in[1];
  const float* W1 = (const float*)d_in[2];
  const float* b1 = (const float*)d_in[3];
  const float* W2 = (const float*)d_in[4];
  const float* b2 = (const float*)d_in[5];
  float* out = (float*)d_out;
  int n = in_sizes[0] / 128;
  int E = in_sizes[1] / 2;

  int *cnt, *rp, *ofs, *bsum;
  float *dinv, *invrs, *y, *t, *u, *G;
  float2* csr;
  cudaGetSymbolAddress((void**)&cnt,   g_cnt);
  cudaGetSymbolAddress((void**)&rp,    g_rp);
  cudaGetSymbolAddress((void**)&ofs,   g_ofs);
  cudaGetSymbolAddress((void**)&bsum,  g_bsum);
  cudaGetSymbolAddress((void**)&dinv,  g_dinv);
  cudaGetSymbolAddress((void**)&invrs, g_invrs);
  cudaGetSymbolAddress((void**)&csr,   g_csr);
  cudaGetSymbolAddress((void**)&y,     g_y);
  cudaGetSymbolAddress((void**)&t,     g_t);
  cudaGetSymbolAddress((void**)&u,     g_u);
  cudaGetSymbolAddress((void**)&G,     g_G);

  const int TB = 256;
  int gN   = (n + TB - 1) / TB;
  int gE   = (E + TB - 1) / TB;
  int gR4  = (n * 4 + TB - 1) / TB;   // spmm: 4 threads per row
  int gW   = (n * 32 + TB - 1) / TB;
  int gG   = (n + 127) / 128;
  int nb   = (n + 1023) / 1024;

  // CSR build (counting sort by dst); degree hist doubles as gcn_norm degree
  k_zero2<<<gN, TB>>>(cnt, ofs, n);
  k_hist<<<gE, TB>>>(ei, cnt, E);
  k_dinv<<<gN, TB>>>(cnt, dinv, n);
  k_scan1<<<nb, 1024>>>(cnt, rp, bsum, n);
  k_scan2<<<1, 64>>>(bsum, nb);
  k_scan3<<<nb, 1024>>>(rp, bsum, n);
  k_fill<<<gE, TB>>>(ei, dinv, rp, ofs, csr, E);

  // row-normalize scale + layer-1 projections
  k_invrs<<<gW, TB>>>(x, invrs, n);
  k_gemm1<<<gG, 256>>>(x, W1, invrs, y, n);

  // layer-1 Horner: G0 = relu(y0 + A(y1 + A(y2 + A*y3)) + b1)
  k_spmm<<<gR4, TB>>>(rp, cnt, csr, (const float4*)(y + 3 * n * 16),
                      (const float4*)(y + 2 * n * 16), nullptr, (float4*)t, n);
  k_spmm<<<gR4, TB>>>(rp, cnt, csr, (const float4*)t,
                      (const float4*)(y + 1 * n * 16), nullptr, (float4*)u, n);
  k_spmm<<<gR4, TB>>>(rp, cnt, csr, (const float4*)u,
                      (const float4*)y, b1, (float4*)G, n);

  // layer-2 hops: G[k+1] = A * G[k]
  for (int k = 0; k < 3; k++) {
    k_spmm<<<gR4, TB>>>(rp, cnt, csr, (const float4*)(G + k * n * 16),
                        nullptr, nullptr, (float4*)(G + (k + 1) * n * 16), n);
  }

  // combine + bias
  k_gemm2<<<gG, 256>>>(G, W2, b2, out, n);
}